// round 14
// baseline (speedup 1.0000x reference)
#include <cuda_runtime.h>
#include <cuda_fp16.h>
#include <cstdint>

#define N_BATCH 4
#define SEQ     2048
#define EMBED   1024
#define HEADS   16
#define HDIM    64
#define SCALE   (1.0f/32.0f)   // 1/sqrt(EMBED) — folded into Q (power of 2, exact)
#define NITER   (SEQ / 64)     // 32 kv tiles of 64

#define RWS 36                 // row stride in 32-bit words (72 halves, 144 B)

// scratch: fp16 attention output, mask bits, fp16 K / V^T / W
__device__ __half   g_attn[N_BATCH * SEQ * EMBED];
__device__ unsigned g_mbits[N_BATCH * SEQ * (SEQ / 32)];
__device__ __half   g_kh[N_BATCH * SEQ * EMBED];
__device__ __half   g_vt[N_BATCH * HEADS * HDIM * SEQ];   // [n][h][d][s]
__device__ __half   g_wh[EMBED * EMBED];

// ---------------------------------------------------------------------------
// helpers (family-common PTX only)
// ---------------------------------------------------------------------------
__device__ __forceinline__ uint32_t smem_u32(const void* p) {
    uint32_t a;
    asm("{ .reg .u64 t; cvta.to.shared.u64 t, %1; cvt.u32.u64 %0, t; }" : "=r"(a) : "l"(p));
    return a;
}
__device__ __forceinline__ void cp16(uint32_t dst, const void* src) {
    asm volatile("cp.async.cg.shared.global [%0], [%1], 16;" :: "r"(dst), "l"(src));
}
#define CP_COMMIT()  asm volatile("cp.async.commit_group;" ::: "memory")
#define CP_WAITG(n)  asm volatile("cp.async.wait_group %0;" :: "n"(n) : "memory")

__device__ __forceinline__ uint32_t h2b(__half2 h) { return *(uint32_t*)&h; }

// m16n8k16 fp16 mma, fp32 accum, D += A*B (C aliases D)
__device__ __forceinline__ void mma16(float* d, const uint32_t* a, uint32_t b0, uint32_t b1) {
    asm volatile(
        "mma.sync.aligned.m16n8k16.row.col.f32.f16.f16.f32 "
        "{%0,%1,%2,%3}, {%4,%5,%6,%7}, {%8,%9}, {%0,%1,%2,%3};"
        : "+f"(d[0]), "+f"(d[1]), "+f"(d[2]), "+f"(d[3])
        : "r"(a[0]), "r"(a[1]), "r"(a[2]), "r"(a[3]), "r"(b0), "r"(b1));
}
__device__ __forceinline__ void ldsm4(uint32_t& r0, uint32_t& r1, uint32_t& r2, uint32_t& r3,
                                      uint32_t addr) {
    asm volatile("ldmatrix.sync.aligned.m8n8.x4.shared.b16 {%0,%1,%2,%3}, [%4];"
        : "=r"(r0), "=r"(r1), "=r"(r2), "=r"(r3) : "r"(addr));
}

// ---------------------------------------------------------------------------
// prepass 1 (no smem, elementwise): [0,4096) cvt K; [4096,4608) cvt W;
//                                   [4608,6656) mask bits. 256 thr/block.
// ---------------------------------------------------------------------------
__global__ void prepass_elem_kernel(const float* __restrict__ keys,
                                    const float* __restrict__ W,
                                    const int*   __restrict__ mask)
{
    const int b   = blockIdx.x;
    const int tid = threadIdx.x;

    if (b < 4608) {
        const float* src = (b < 4096) ? keys : W;
        __half*      dst = (b < 4096) ? g_kh : g_wh;
        const size_t base = ((size_t)(b < 4096 ? b : b - 4096) * 256 + tid) * 8;
        float4 v0 = *(const float4*)(src + base);
        float4 v1 = *(const float4*)(src + base + 4);
        uint4 o;
        o.x = h2b(__floats2half2_rn(v0.x, v0.y));
        o.y = h2b(__floats2half2_rn(v0.z, v0.w));
        o.z = h2b(__floats2half2_rn(v1.x, v1.y));
        o.w = h2b(__floats2half2_rn(v1.z, v1.w));
        *(uint4*)(dst + base) = o;
    } else {
        const size_t w = (size_t)(b - 4608) * 256 + tid;
        const int4* p = (const int4*)mask + w * 8;
        unsigned bits = 0;
        #pragma unroll
        for (int i = 0; i < 8; i++) {
            int4 v = p[i];
            bits |= (v.x != 0 ? 1u : 0u) << (i * 4 + 0);
            bits |= (v.y != 0 ? 1u : 0u) << (i * 4 + 1);
            bits |= (v.z != 0 ? 1u : 0u) << (i * 4 + 2);
            bits |= (v.w != 0 ? 1u : 0u) << (i * 4 + 3);
        }
        g_mbits[w] = bits;
    }
}

// ---------------------------------------------------------------------------
// prepass 2: V [n][s][h*64+d] fp32 -> V^T [n][h][d][s] fp16 (64x64 smem tiles)
// ---------------------------------------------------------------------------
__global__ void vt_kernel(const float* __restrict__ V)
{
    __shared__ float tile[64][68];
    const int tid = threadIdx.x;
    const int s0  = blockIdx.x * 64;
    const int h   = blockIdx.y;
    const int n   = blockIdx.z;

    const int sr = tid >> 2, c = (tid & 3) * 16;
    const float* src = V + ((size_t)(n * SEQ + s0 + sr)) * EMBED + h * HDIM + c;
    #pragma unroll
    for (int j = 0; j < 4; j++)
        *(float4*)&tile[sr][c + j * 4] = *(const float4*)(src + j * 4);
    __syncthreads();

    const int dr = tid >> 2, sc = (tid & 3) * 16;
    __half* dst = g_vt + ((size_t)((n * HEADS + h) * HDIM + dr)) * SEQ + s0 + sc;
    #pragma unroll
    for (int j = 0; j < 8; j++) {
        __half2 p = __floats2half2_rn(tile[sc + 2 * j][dr], tile[sc + 2 * j + 1][dr]);
        *(uint32_t*)(dst + 2 * j) = h2b(p);
    }
}

// ---------------------------------------------------------------------------
// fp16 flash attention: identical math to R13; ONLY change is occupancy 3
// (__launch_bounds__(256,3) caps regs at 84; smem 3 CTAs x 55296 = 166 KB).
// grid (16, HEADS, N_BATCH), 256 threads (8 warps), warp w owns q-rows w*16..+15
// ---------------------------------------------------------------------------
#define STG_B 18432
#define ATTN_SMEM (3 * STG_B)

__global__ __launch_bounds__(256, 3) void attn_kernel(
    const float* __restrict__ query)
{
    extern __shared__ uint32_t sw[];
    const int tid  = threadIdx.x;
    const int w    = tid >> 5;
    const int lane = tid & 31;
    const int gr   = lane >> 2;      // 0..7
    const int tig  = lane & 3;       // 0..3

    const int r0 = blockIdx.x * 128;
    const int h  = blockIdx.y;
    const int n  = blockIdx.z;
    const int qrow = r0 + w * 16 + gr;

    // ---- cp.async src/dst: K rows (key-major), V^T rows (d-major) ----
    const int lr = tid >> 2;              // 0..63
    const __half* ksrc0 = g_kh + ((size_t)n * SEQ + lr) * EMBED + h * HDIM + (tid & 3) * 16;
    const __half* vsrc0 = g_vt + ((size_t)((n * HEADS + h) * HDIM + lr)) * SEQ + (tid & 3) * 16;
    const uint32_t kdst0 = smem_u32(sw + lr * RWS + (tid & 3) * 8);
    const uint32_t vdst0 = kdst0 + 2304 * 4;

    // ---- ldmatrix lane bases (B-operand pattern for K and V) ----
    const int rsel = ((lane >> 4) & 1) * 8 + (lane & 7);
    const int wo   = ((lane >> 3) & 1) * 4;
    const uint32_t kls0 = smem_u32(sw + rsel * RWS + wo);
    const uint32_t vls0 = kls0 + 2304 * 4;

    // ---- Q fragments: fp32 gmem -> fp16x2 regs, pre-scaled by 1/32 (exact) ----
    uint32_t qf[4][4];
    {
        const float* qa = query + ((size_t)n * SEQ + qrow) * EMBED + h * HDIM;
        const float* qc = qa + 8 * EMBED;
        #pragma unroll
        for (int dk = 0; dk < 4; dk++) {
            float2 f;
            f = *(const float2*)&qa[16 * dk + 2 * tig];
            qf[dk][0] = h2b(__floats2half2_rn(f.x * SCALE, f.y * SCALE));
            f = *(const float2*)&qc[16 * dk + 2 * tig];
            qf[dk][1] = h2b(__floats2half2_rn(f.x * SCALE, f.y * SCALE));
            f = *(const float2*)&qa[16 * dk + 2 * tig + 8];
            qf[dk][2] = h2b(__floats2half2_rn(f.x * SCALE, f.y * SCALE));
            f = *(const float2*)&qc[16 * dk + 2 * tig + 8];
            qf[dk][3] = h2b(__floats2half2_rn(f.x * SCALE, f.y * SCALE));
        }
    }

    // prologue: tiles 0 and 1 into stages 0 and 1
    cp16(kdst0, ksrc0);              cp16(kdst0 + 16, ksrc0 + 8);
    cp16(vdst0, vsrc0);              cp16(vdst0 + 16, vsrc0 + 8);
    CP_COMMIT();
    cp16(kdst0 + STG_B, ksrc0 + 64 * EMBED);      cp16(kdst0 + STG_B + 16, ksrc0 + 64 * EMBED + 8);
    cp16(vdst0 + STG_B, vsrc0 + 64);              cp16(vdst0 + STG_B + 16, vsrc0 + 64 + 8);
    CP_COMMIT();

    float o[8][4];
    #pragma unroll
    for (int nt = 0; nt < 8; nt++)
        #pragma unroll
        for (int q = 0; q < 4; q++) o[nt][q] = 0.0f;
    float lsA[2] = {0.0f, 0.0f};
    float lsB[2] = {0.0f, 0.0f};

    const unsigned* mrow0 = &g_mbits[((size_t)n * SEQ + qrow) * (SEQ / 32)];
    const unsigned* mrow1 = mrow0 + 8 * (SEQ / 32);

    for (int iter = 0; iter < NITER; iter++) {
        CP_WAITG(1);
        __syncthreads();
        if (iter + 2 < NITER) {
            const int ps = (iter + 2) % 3;
            const __half* ks = ksrc0 + (size_t)(iter + 2) * 64 * EMBED;
            const __half* vs = vsrc0 + (size_t)(iter + 2) * 64;
            cp16(kdst0 + ps * STG_B, ks);      cp16(kdst0 + ps * STG_B + 16, ks + 8);
            cp16(vdst0 + ps * STG_B, vs);      cp16(vdst0 + ps * STG_B + 16, vs + 8);
        }
        CP_COMMIT();

        const int st = iter % 3;
        const uint32_t kst = kls0 + st * STG_B;
        const uint32_t vst = vls0 + st * STG_B;
        const uint2 mAv = *(const uint2*)(mrow0 + iter * 2);
        const uint2 mBv = *(const uint2*)(mrow1 + iter * 2);
        const unsigned mwA[2] = { mAv.x, mAv.y };
        const unsigned mwB[2] = { mBv.x, mBv.y };

        #pragma unroll
        for (int hh = 0; hh < 2; hh++) {
            float s[4][4];
            #pragma unroll
            for (int ln = 0; ln < 4; ln++)
                #pragma unroll
                for (int q = 0; q < 4; q++) s[ln][q] = 0.0f;
            #pragma unroll
            for (int dk = 0; dk < 4; dk++) {
                #pragma unroll
                for (int kp = 0; kp < 2; kp++) {
                    uint32_t b0, b1, b2, b3;
                    ldsm4(b0, b1, b2, b3, kst + (((hh * 2 + kp) * 16) * RWS + 8 * dk) * 4);
                    mma16(s[2 * kp],     qf[dk], b0, b1);
                    mma16(s[2 * kp + 1], qf[dk], b2, b3);
                }
            }

            uint32_t pa[2][4];
            #pragma unroll
            for (int c = 0; c < 2; c++) {
                float sa0 = 0.0f, sb0 = 0.0f;
                #pragma unroll
                for (int j = 0; j < 2; j++) {
                    const int ln = 2 * c + j;
                    const int sh = ln * 8 + 2 * tig;
                    const unsigned wA = mwA[hh], wB = mwB[hh];
                    float e0 = ((wA >> sh) & 1u)       ? __expf(s[ln][0]) : 0.0f;
                    float e1 = ((wA >> (sh + 1)) & 1u) ? __expf(s[ln][1]) : 0.0f;
                    float e2 = ((wB >> sh) & 1u)       ? __expf(s[ln][2]) : 0.0f;
                    float e3 = ((wB >> (sh + 1)) & 1u) ? __expf(s[ln][3]) : 0.0f;
                    const __half2 hA = __floats2half2_rn(e0, e1);
                    const __half2 hB = __floats2half2_rn(e2, e3);
                    const float2 fA = __half22float2(hA);
                    const float2 fB = __half22float2(hB);
                    sa0 += fA.x + fA.y;
                    sb0 += fB.x + fB.y;
                    pa[c][2 * j]     = h2b(hA);
                    pa[c][2 * j + 1] = h2b(hB);
                }
                lsA[c] += sa0;
                lsB[c] += sb0;
            }

            #pragma unroll
            for (int c = 0; c < 2; c++) {
                #pragma unroll
                for (int np = 0; np < 4; np++) {
                    uint32_t b0, b1, b2, b3;
                    ldsm4(b0, b1, b2, b3, vst + ((np * 16) * RWS + 8 * (hh * 2 + c)) * 4);
                    mma16(o[2 * np],     pa[c], b0, b1);
                    mma16(o[2 * np + 1], pa[c], b2, b3);
                }
            }
        }
    }

    float ls0 = lsA[0] + lsA[1];
    float ls1 = lsB[0] + lsB[1];
    ls0 += __shfl_xor_sync(0xffffffffu, ls0, 1);
    ls0 += __shfl_xor_sync(0xffffffffu, ls0, 2);
    ls1 += __shfl_xor_sync(0xffffffffu, ls1, 1);
    ls1 += __shfl_xor_sync(0xffffffffu, ls1, 2);
    const float i0 = 1.0f / ls0, i1 = 1.0f / ls1;
    __half* ob0 = g_attn + ((size_t)n * SEQ + qrow) * EMBED + h * HDIM;
    __half* ob1 = ob0 + 8 * EMBED;
    #pragma unroll
    for (int nt = 0; nt < 8; nt++) {
        *(uint32_t*)(ob0 + nt * 8 + 2 * tig) = h2b(__floats2half2_rn(o[nt][0] * i0, o[nt][1] * i0));
        *(uint32_t*)(ob1 + nt * 8 + 2 * tig) = h2b(__floats2half2_rn(o[nt][2] * i1, o[nt][3] * i1));
    }
}

// ---------------------------------------------------------------------------
// fp16 projection, 512 threads (unchanged from R13): out = X @ W^T + b
// CTA tile 128m x 128n; 16 warps (warp tile m16 x n64); 3-stage cp.async ring.
// ---------------------------------------------------------------------------
#define PRJ_STG_B 36864
#define XW_SMEM (3 * PRJ_STG_B)

__global__ __launch_bounds__(512, 1) void proj_kernel(
    const float* __restrict__ bias,
    float*       __restrict__ out)
{
    extern __shared__ uint32_t sw[];
    const int tid  = threadIdx.x;
    const int wid  = tid >> 5;       // 0..15
    const int lane = tid & 31;
    const int gr   = lane >> 2;
    const int tig  = lane & 3;
    const int wm   = wid >> 1;       // 0..7  -> m rows wm*16
    const int wn   = wid & 1;        // 0..1  -> n cols wn*64

    const int m0 = blockIdx.x * 128;
    const int j0 = blockIdx.y * 128;

    const int xr = tid >> 2;
    const int xc = (tid & 3) * 16;
    const __half* xsrc0 = g_attn + ((size_t)(m0 + xr)) * EMBED + xc;
    const __half* wsrc0 = g_wh + ((size_t)(j0 + xr)) * EMBED + xc;
    const uint32_t xdst0 = smem_u32(sw + xr * RWS) + (tid & 3) * 32;
    const uint32_t wdst0 = xdst0 + 4608 * 4;

    const int rselA = (lane & 7) + ((lane >> 3) & 1) * 8;
    const int woA   = ((lane >> 4) & 1) * 4;
    const uint32_t xls0 = smem_u32(sw + (wm * 16 + rselA) * RWS + woA);
    const int rselB = ((lane >> 4) & 1) * 8 + (lane & 7);
    const int woB   = ((lane >> 3) & 1) * 4;
    const uint32_t wls0 = smem_u32(sw + (wn * 64 + rselB) * RWS + woB) + 4608 * 4;

    cp16(xdst0, xsrc0);              cp16(xdst0 + 16, xsrc0 + 8);
    cp16(wdst0, wsrc0);              cp16(wdst0 + 16, wsrc0 + 8);
    CP_COMMIT();
    cp16(xdst0 + PRJ_STG_B, xsrc0 + 64);      cp16(xdst0 + PRJ_STG_B + 16, xsrc0 + 64 + 8);
    cp16(wdst0 + PRJ_STG_B, wsrc0 + 64);      cp16(wdst0 + PRJ_STG_B + 16, wsrc0 + 64 + 8);
    CP_COMMIT();

    float acc[8][4];
    #pragma unroll
    for (int nt = 0; nt < 8; nt++)
        #pragma unroll
        for (int q = 0; q < 4; q++) acc[nt][q] = 0.0f;

    for (int kc = 0; kc < EMBED / 64; kc++) {
        CP_WAITG(1);
        __syncthreads();
        if (kc + 2 < EMBED / 64) {
            const int ps = (kc + 2) % 3;
            const int k1 = (kc + 2) * 64;
            cp16(xdst0 + ps * PRJ_STG_B, xsrc0 + k1);
            cp16(xdst0 + ps * PRJ_STG_B + 16, xsrc0 + k1 + 8);
            cp16(wdst0 + ps * PRJ_STG_B, wsrc0 + k1);
            cp16(wdst0 + ps * PRJ_STG_B + 16, wsrc0 + k1 + 8);
        }
        CP_COMMIT();

        const int st = kc % 3;
        const uint32_t xst = xls0 + st * PRJ_STG_B;
        const uint32_t wst = wls0 + st * PRJ_STG_B;
        #pragma unroll
        for (int dk = 0; dk < 4; dk++) {
            uint32_t a[4];
            ldsm4(a[0], a[1], a[2], a[3], xst + (8 * dk) * 4);
            #pragma unroll
            for (int np = 0; np < 4; np++) {
                uint32_t b0, b1, b2, b3;
                ldsm4(b0, b1, b2, b3, wst + ((np * 16) * RWS + 8 * dk) * 4);
                mma16(acc[2 * np],     a, b0, b1);
                mma16(acc[2 * np + 1], a, b2, b3);
            }
        }
    }

    const int mrow = m0 + wm * 16 + gr;
    const int jbase = j0 + wn * 64;
    float* ob0 = out + (size_t)mrow * EMBED + jbase;
    float* ob1 = ob0 + 8 * EMBED;
    #pragma unroll
    for (int nt = 0; nt < 8; nt++) {
        const float2 bb = *(const float2*)&bias[jbase + nt * 8 + 2 * tig];
        *(float2*)&ob0[nt * 8 + 2 * tig] = make_float2(acc[nt][0] + bb.x, acc[nt][1] + bb.y);
        *(float2*)&ob1[nt * 8 + 2 * tig] = make_float2(acc[nt][2] + bb.x, acc[nt][3] + bb.y);
    }
}

// ---------------------------------------------------------------------------
extern "C" void kernel_launch(void* const* d_in, const int* in_sizes, int n_in,
                              void* d_out, int out_size)
{
    const float* values = (const float*)d_in[0];
    const float* keys   = (const float*)d_in[1];
    const float* query  = (const float*)d_in[2];
    const int*   mask   = (const int*)  d_in[3];
    const float* W_out  = (const float*)d_in[4];
    const float* b_out  = (const float*)d_in[5];
    float*       out    = (float*)d_out;

    cudaFuncSetAttribute(attn_kernel,
                         cudaFuncAttributeMaxDynamicSharedMemorySize, ATTN_SMEM);
    cudaFuncSetAttribute(proj_kernel,
                         cudaFuncAttributeMaxDynamicSharedMemorySize, XW_SMEM);

    prepass_elem_kernel<<<6656, 256>>>(keys, W_out, mask);
    vt_kernel<<<dim3(SEQ / 64, HEADS, N_BATCH), 256>>>(values);
    attn_kernel<<<dim3(SEQ / 128, HEADS, N_BATCH), 256, ATTN_SMEM>>>(query);
    proj_kernel<<<dim3((N_BATCH * SEQ) / 128, EMBED / 128), 512, XW_SMEM>>>(b_out, out);
}

// round 17
// speedup vs baseline: 1.1947x; 1.1947x over previous
#include <cuda_runtime.h>
#include <cuda_fp16.h>
#include <cstdint>

#define N_BATCH 4
#define SEQ     2048
#define EMBED   1024
#define HEADS   16
#define HDIM    64
// Q pre-scale: log2(e)/32 — S emerges in log2 domain, exp(x/32) == 2^S
#define QSCALE  (1.4426950408889634f / 32.0f)
#define NITER   (SEQ / 64)     // 32 kv tiles of 64

#define RWS 36                 // row stride in 32-bit words (72 halves, 144 B)

// scratch: fp16 attention output, mask bits, fp16 K / V^T / W
__device__ __half   g_attn[N_BATCH * SEQ * EMBED];
__device__ unsigned g_mbits[N_BATCH * SEQ * (SEQ / 32)];
__device__ __half   g_kh[N_BATCH * SEQ * EMBED];
__device__ __half   g_vt[N_BATCH * HEADS * HDIM * SEQ];   // [n][h][d][s]
__device__ __half   g_wh[EMBED * EMBED];

// ---------------------------------------------------------------------------
// helpers (family-common PTX only)
// ---------------------------------------------------------------------------
__device__ __forceinline__ uint32_t smem_u32(const void* p) {
    uint32_t a;
    asm("{ .reg .u64 t; cvta.to.shared.u64 t, %1; cvt.u32.u64 %0, t; }" : "=r"(a) : "l"(p));
    return a;
}
__device__ __forceinline__ void cp16(uint32_t dst, const void* src) {
    asm volatile("cp.async.cg.shared.global [%0], [%1], 16;" :: "r"(dst), "l"(src));
}
#define CP_COMMIT()  asm volatile("cp.async.commit_group;" ::: "memory")
#define CP_WAITG(n)  asm volatile("cp.async.wait_group %0;" :: "n"(n) : "memory")

__device__ __forceinline__ uint32_t h2b(__half2 h) { return *(uint32_t*)&h; }

// packed fp16 2^x (one MUFU op for two exps)
__device__ __forceinline__ uint32_t ex2_f16x2(uint32_t x) {
    uint32_t r;
    asm("ex2.approx.f16x2 %0, %1;" : "=r"(r) : "r"(x));
    return r;
}

// m16n8k16 fp16 mma, fp32 accum, D += A*B (C aliases D)
__device__ __forceinline__ void mma16(float* d, const uint32_t* a, uint32_t b0, uint32_t b1) {
    asm volatile(
        "mma.sync.aligned.m16n8k16.row.col.f32.f16.f16.f32 "
        "{%0,%1,%2,%3}, {%4,%5,%6,%7}, {%8,%9}, {%0,%1,%2,%3};"
        : "+f"(d[0]), "+f"(d[1]), "+f"(d[2]), "+f"(d[3])
        : "r"(a[0]), "r"(a[1]), "r"(a[2]), "r"(a[3]), "r"(b0), "r"(b1));
}
__device__ __forceinline__ void ldsm4(uint32_t& r0, uint32_t& r1, uint32_t& r2, uint32_t& r3,
                                      uint32_t addr) {
    asm volatile("ldmatrix.sync.aligned.m8n8.x4.shared.b16 {%0,%1,%2,%3}, [%4];"
        : "=r"(r0), "=r"(r1), "=r"(r2), "=r"(r3) : "r"(addr));
}

// ---------------------------------------------------------------------------
// prepass 1 (no smem, elementwise): [0,4096) cvt K; [4096,4608) cvt W;
//                                   [4608,6656) mask bits. 256 thr/block.
// ---------------------------------------------------------------------------
__global__ void prepass_elem_kernel(const float* __restrict__ keys,
                                    const float* __restrict__ W,
                                    const int*   __restrict__ mask)
{
    const int b   = blockIdx.x;
    const int tid = threadIdx.x;

    if (b < 4608) {
        const float* src = (b < 4096) ? keys : W;
        __half*      dst = (b < 4096) ? g_kh : g_wh;
        const size_t base = ((size_t)(b < 4096 ? b : b - 4096) * 256 + tid) * 8;
        float4 v0 = *(const float4*)(src + base);
        float4 v1 = *(const float4*)(src + base + 4);
        uint4 o;
        o.x = h2b(__floats2half2_rn(v0.x, v0.y));
        o.y = h2b(__floats2half2_rn(v0.z, v0.w));
        o.z = h2b(__floats2half2_rn(v1.x, v1.y));
        o.w = h2b(__floats2half2_rn(v1.z, v1.w));
        *(uint4*)(dst + base) = o;
    } else {
        const size_t w = (size_t)(b - 4608) * 256 + tid;
        const int4* p = (const int4*)mask + w * 8;
        unsigned bits = 0;
        #pragma unroll
        for (int i = 0; i < 8; i++) {
            int4 v = p[i];
            bits |= (v.x != 0 ? 1u : 0u) << (i * 4 + 0);
            bits |= (v.y != 0 ? 1u : 0u) << (i * 4 + 1);
            bits |= (v.z != 0 ? 1u : 0u) << (i * 4 + 2);
            bits |= (v.w != 0 ? 1u : 0u) << (i * 4 + 3);
        }
        g_mbits[w] = bits;
    }
}

// ---------------------------------------------------------------------------
// prepass 2: V [n][s][h*64+d] fp32 -> V^T [n][h][d][s] fp16 (64x64 smem tiles)
// ---------------------------------------------------------------------------
__global__ void vt_kernel(const float* __restrict__ V)
{
    __shared__ float tile[64][68];
    const int tid = threadIdx.x;
    const int s0  = blockIdx.x * 64;
    const int h   = blockIdx.y;
    const int n   = blockIdx.z;

    const int sr = tid >> 2, c = (tid & 3) * 16;
    const float* src = V + ((size_t)(n * SEQ + s0 + sr)) * EMBED + h * HDIM + c;
    #pragma unroll
    for (int j = 0; j < 4; j++)
        *(float4*)&tile[sr][c + j * 4] = *(const float4*)(src + j * 4);
    __syncthreads();

    const int dr = tid >> 2, sc = (tid & 3) * 16;
    __half* dst = g_vt + ((size_t)((n * HEADS + h) * HDIM + dr)) * SEQ + s0 + sc;
    #pragma unroll
    for (int j = 0; j < 8; j++) {
        __half2 p = __floats2half2_rn(tile[sc + 2 * j][dr], tile[sc + 2 * j + 1][dr]);
        *(uint32_t*)(dst + 2 * j) = h2b(p);
    }
}

// ---------------------------------------------------------------------------
// fp16 flash attention (R13 structure, occ 2): ldmatrix fragments,
// register-resident P, fp32-accum, 3-stage cp.async ring.
// NEW: Q pre-scaled by log2e/32; exp via ex2.approx.f16x2 (2 exps / MUFU op).
// grid (16, HEADS, N_BATCH), 256 threads (8 warps), warp w owns q-rows w*16..+15
// ---------------------------------------------------------------------------
#define STG_B 18432
#define ATTN_SMEM (3 * STG_B)

__global__ __launch_bounds__(256, 2) void attn_kernel(
    const float* __restrict__ query)
{
    extern __shared__ uint32_t sw[];
    const int tid  = threadIdx.x;
    const int w    = tid >> 5;
    const int lane = tid & 31;
    const int gr   = lane >> 2;      // 0..7
    const int tig  = lane & 3;       // 0..3

    const int r0 = blockIdx.x * 128;
    const int h  = blockIdx.y;
    const int n  = blockIdx.z;
    const int qrow = r0 + w * 16 + gr;

    // ---- cp.async src/dst: K rows (key-major), V^T rows (d-major) ----
    const int lr = tid >> 2;              // 0..63
    const __half* ksrc0 = g_kh + ((size_t)n * SEQ + lr) * EMBED + h * HDIM + (tid & 3) * 16;
    const __half* vsrc0 = g_vt + ((size_t)((n * HEADS + h) * HDIM + lr)) * SEQ + (tid & 3) * 16;
    const uint32_t kdst0 = smem_u32(sw + lr * RWS + (tid & 3) * 8);
    const uint32_t vdst0 = kdst0 + 2304 * 4;

    // ---- ldmatrix lane bases (B-operand pattern for K and V) ----
    const int rsel = ((lane >> 4) & 1) * 8 + (lane & 7);
    const int wo   = ((lane >> 3) & 1) * 4;
    const uint32_t kls0 = smem_u32(sw + rsel * RWS + wo);
    const uint32_t vls0 = kls0 + 2304 * 4;

    // ---- Q fragments: fp32 gmem -> fp16x2 regs, pre-scaled by log2e/32 ----
    uint32_t qf[4][4];
    {
        const float* qa = query + ((size_t)n * SEQ + qrow) * EMBED + h * HDIM;
        const float* qc = qa + 8 * EMBED;
        #pragma unroll
        for (int dk = 0; dk < 4; dk++) {
            float2 f;
            f = *(const float2*)&qa[16 * dk + 2 * tig];
            qf[dk][0] = h2b(__floats2half2_rn(f.x * QSCALE, f.y * QSCALE));
            f = *(const float2*)&qc[16 * dk + 2 * tig];
            qf[dk][1] = h2b(__floats2half2_rn(f.x * QSCALE, f.y * QSCALE));
            f = *(const float2*)&qa[16 * dk + 2 * tig + 8];
            qf[dk][2] = h2b(__floats2half2_rn(f.x * QSCALE, f.y * QSCALE));
            f = *(const float2*)&qc[16 * dk + 2 * tig + 8];
            qf[dk][3] = h2b(__floats2half2_rn(f.x * QSCALE, f.y * QSCALE));
        }
    }

    // prologue: tiles 0 and 1 into stages 0 and 1
    cp16(kdst0, ksrc0);              cp16(kdst0 + 16, ksrc0 + 8);
    cp16(vdst0, vsrc0);              cp16(vdst0 + 16, vsrc0 + 8);
    CP_COMMIT();
    cp16(kdst0 + STG_B, ksrc0 + 64 * EMBED);      cp16(kdst0 + STG_B + 16, ksrc0 + 64 * EMBED + 8);
    cp16(vdst0 + STG_B, vsrc0 + 64);              cp16(vdst0 + STG_B + 16, vsrc0 + 64 + 8);
    CP_COMMIT();

    float o[8][4];
    #pragma unroll
    for (int nt = 0; nt < 8; nt++)
        #pragma unroll
        for (int q = 0; q < 4; q++) o[nt][q] = 0.0f;
    float lsA[2] = {0.0f, 0.0f};
    float lsB[2] = {0.0f, 0.0f};

    const unsigned* mrow0 = &g_mbits[((size_t)n * SEQ + qrow) * (SEQ / 32)];
    const unsigned* mrow1 = mrow0 + 8 * (SEQ / 32);

    for (int iter = 0; iter < NITER; iter++) {
        CP_WAITG(1);
        __syncthreads();
        if (iter + 2 < NITER) {
            const int ps = (iter + 2) % 3;
            const __half* ks = ksrc0 + (size_t)(iter + 2) * 64 * EMBED;
            const __half* vs = vsrc0 + (size_t)(iter + 2) * 64;
            cp16(kdst0 + ps * STG_B, ks);      cp16(kdst0 + ps * STG_B + 16, ks + 8);
            cp16(vdst0 + ps * STG_B, vs);      cp16(vdst0 + ps * STG_B + 16, vs + 8);
        }
        CP_COMMIT();

        const int st = iter % 3;
        const uint32_t kst = kls0 + st * STG_B;
        const uint32_t vst = vls0 + st * STG_B;
        const uint2 mAv = *(const uint2*)(mrow0 + iter * 2);
        const uint2 mBv = *(const uint2*)(mrow1 + iter * 2);
        const unsigned mwA[2] = { mAv.x, mAv.y };
        const unsigned mwB[2] = { mBv.x, mBv.y };

        #pragma unroll
        for (int hh = 0; hh < 2; hh++) {
            float s[4][4];
            #pragma unroll
            for (int ln = 0; ln < 4; ln++)
                #pragma unroll
                for (int q = 0; q < 4; q++) s[ln][q] = 0.0f;
            #pragma unroll
            for (int dk = 0; dk < 4; dk++) {
                #pragma unroll
                for (int kp = 0; kp < 2; kp++) {
                    uint32_t b0, b1, b2, b3;
                    ldsm4(b0, b1, b2, b3, kst + (((hh * 2 + kp) * 16) * RWS + 8 * dk) * 4);
                    mma16(s[2 * kp],     qf[dk], b0, b1);
                    mma16(s[2 * kp + 1], qf[dk], b2, b3);
                }
            }

            // ---- masked 2^s via ex2.approx.f16x2 -> fp16 A-fragments ----
            uint32_t pa[2][4];
            #pragma unroll
            for (int c = 0; c < 2; c++) {
                float sa0 = 0.0f, sb0 = 0.0f;
                #pragma unroll
                for (int j = 0; j < 2; j++) {
                    const int ln = 2 * c + j;
                    const int sh = ln * 8 + 2 * tig;
                    const unsigned wA = mwA[hh], wB = mwB[hh];
                    const float a0 = ((wA >> sh) & 1u)       ? s[ln][0] : -1000.0f;
                    const float a1 = ((wA >> (sh + 1)) & 1u) ? s[ln][1] : -1000.0f;
                    const float a2 = ((wB >> sh) & 1u)       ? s[ln][2] : -1000.0f;
                    const float a3 = ((wB >> (sh + 1)) & 1u) ? s[ln][3] : -1000.0f;
                    const uint32_t eA = ex2_f16x2(h2b(__floats2half2_rn(a0, a1)));
                    const uint32_t eB = ex2_f16x2(h2b(__floats2half2_rn(a2, a3)));
                    const float2 fA = __half22float2(*(const __half2*)&eA);
                    const float2 fB = __half22float2(*(const __half2*)&eB);
                    sa0 += fA.x + fA.y;
                    sb0 += fB.x + fB.y;
                    pa[c][2 * j]     = eA;   // a0 / a2 (rows gr,   k lo/hi)
                    pa[c][2 * j + 1] = eB;   // a1 / a3 (rows gr+8, k lo/hi)
                }
                lsA[c] += sa0;
                lsB[c] += sb0;
            }

            #pragma unroll
            for (int c = 0; c < 2; c++) {
                #pragma unroll
                for (int np = 0; np < 4; np++) {
                    uint32_t b0, b1, b2, b3;
                    ldsm4(b0, b1, b2, b3, vst + ((np * 16) * RWS + 8 * (hh * 2 + c)) * 4);
                    mma16(o[2 * np],     pa[c], b0, b1);
                    mma16(o[2 * np + 1], pa[c], b2, b3);
                }
            }
        }
    }

    float ls0 = lsA[0] + lsA[1];
    float ls1 = lsB[0] + lsB[1];
    ls0 += __shfl_xor_sync(0xffffffffu, ls0, 1);
    ls0 += __shfl_xor_sync(0xffffffffu, ls0, 2);
    ls1 += __shfl_xor_sync(0xffffffffu, ls1, 1);
    ls1 += __shfl_xor_sync(0xffffffffu, ls1, 2);
    const float i0 = 1.0f / ls0, i1 = 1.0f / ls1;
    __half* ob0 = g_attn + ((size_t)n * SEQ + qrow) * EMBED + h * HDIM;
    __half* ob1 = ob0 + 8 * EMBED;
    #pragma unroll
    for (int nt = 0; nt < 8; nt++) {
        *(uint32_t*)(ob0 + nt * 8 + 2 * tig) = h2b(__floats2half2_rn(o[nt][0] * i0, o[nt][1] * i0));
        *(uint32_t*)(ob1 + nt * 8 + 2 * tig) = h2b(__floats2half2_rn(o[nt][2] * i1, o[nt][3] * i1));
    }
}

// ---------------------------------------------------------------------------
// fp16 projection, 512 threads (unchanged from R13): out = X @ W^T + b
// CTA tile 128m x 128n; 16 warps (warp tile m16 x n64); 3-stage cp.async ring.
// ---------------------------------------------------------------------------
#define PRJ_STG_B 36864
#define XW_SMEM (3 * PRJ_STG_B)

__global__ __launch_bounds__(512, 1) void proj_kernel(
    const float* __restrict__ bias,
    float*       __restrict__ out)
{
    extern __shared__ uint32_t sw[];
    const int tid  = threadIdx.x;
    const int wid  = tid >> 5;       // 0..15
    const int lane = tid & 31;
    const int gr   = lane >> 2;
    const int tig  = lane & 3;
    const int wm   = wid >> 1;       // 0..7  -> m rows wm*16
    const int wn   = wid & 1;        // 0..1  -> n cols wn*64

    const int m0 = blockIdx.x * 128;
    const int j0 = blockIdx.y * 128;

    const int xr = tid >> 2;
    const int xc = (tid & 3) * 16;
    const __half* xsrc0 = g_attn + ((size_t)(m0 + xr)) * EMBED + xc;
    const __half* wsrc0 = g_wh + ((size_t)(j0 + xr)) * EMBED + xc;
    const uint32_t xdst0 = smem_u32(sw + xr * RWS) + (tid & 3) * 32;
    const uint32_t wdst0 = xdst0 + 4608 * 4;

    const int rselA = (lane & 7) + ((lane >> 3) & 1) * 8;
    const int woA   = ((lane >> 4) & 1) * 4;
    const uint32_t xls0 = smem_u32(sw + (wm * 16 + rselA) * RWS + woA);
    const int rselB = ((lane >> 4) & 1) * 8 + (lane & 7);
    const int woB   = ((lane >> 3) & 1) * 4;
    const uint32_t wls0 = smem_u32(sw + (wn * 64 + rselB) * RWS + woB) + 4608 * 4;

    cp16(xdst0, xsrc0);              cp16(xdst0 + 16, xsrc0 + 8);
    cp16(wdst0, wsrc0);              cp16(wdst0 + 16, wsrc0 + 8);
    CP_COMMIT();
    cp16(xdst0 + PRJ_STG_B, xsrc0 + 64);      cp16(xdst0 + PRJ_STG_B + 16, xsrc0 + 64 + 8);
    cp16(wdst0 + PRJ_STG_B, wsrc0 + 64);      cp16(wdst0 + PRJ_STG_B + 16, wsrc0 + 64 + 8);
    CP_COMMIT();

    float acc[8][4];
    #pragma unroll
    for (int nt = 0; nt < 8; nt++)
        #pragma unroll
        for (int q = 0; q < 4; q++) acc[nt][q] = 0.0f;

    for (int kc = 0; kc < EMBED / 64; kc++) {
        CP_WAITG(1);
        __syncthreads();
        if (kc + 2 < EMBED / 64) {
            const int ps = (kc + 2) % 3;
            const int k1 = (kc + 2) * 64;
            cp16(xdst0 + ps * PRJ_STG_B, xsrc0 + k1);
            cp16(xdst0 + ps * PRJ_STG_B + 16, xsrc0 + k1 + 8);
            cp16(wdst0 + ps * PRJ_STG_B, wsrc0 + k1);
            cp16(wdst0 + ps * PRJ_STG_B + 16, wsrc0 + k1 + 8);
        }
        CP_COMMIT();

        const int st = kc % 3;
        const uint32_t xst = xls0 + st * PRJ_STG_B;
        const uint32_t wst = wls0 + st * PRJ_STG_B;
        #pragma unroll
        for (int dk = 0; dk < 4; dk++) {
            uint32_t a[4];
            ldsm4(a[0], a[1], a[2], a[3], xst + (8 * dk) * 4);
            #pragma unroll
            for (int np = 0; np < 4; np++) {
                uint32_t b0, b1, b2, b3;
                ldsm4(b0, b1, b2, b3, wst + ((np * 16) * RWS + 8 * dk) * 4);
                mma16(acc[2 * np],     a, b0, b1);
                mma16(acc[2 * np + 1], a, b2, b3);
            }
        }
    }

    const int mrow = m0 + wm * 16 + gr;
    const int jbase = j0 + wn * 64;
    float* ob0 = out + (size_t)mrow * EMBED + jbase;
    float* ob1 = ob0 + 8 * EMBED;
    #pragma unroll
    for (int nt = 0; nt < 8; nt++) {
        const float2 bb = *(const float2*)&bias[jbase + nt * 8 + 2 * tig];
        *(float2*)&ob0[nt * 8 + 2 * tig] = make_float2(acc[nt][0] + bb.x, acc[nt][1] + bb.y);
        *(float2*)&ob1[nt * 8 + 2 * tig] = make_float2(acc[nt][2] + bb.x, acc[nt][3] + bb.y);
    }
}

// ---------------------------------------------------------------------------
extern "C" void kernel_launch(void* const* d_in, const int* in_sizes, int n_in,
                              void* d_out, int out_size)
{
    const float* values = (const float*)d_in[0];
    const float* keys   = (const float*)d_in[1];
    const float* query  = (const float*)d_in[2];
    const int*   mask   = (const int*)  d_in[3];
    const float* W_out  = (const float*)d_in[4];
    const float* b_out  = (const float*)d_in[5];
    float*       out    = (float*)d_out;

    cudaFuncSetAttribute(attn_kernel,
                         cudaFuncAttributeMaxDynamicSharedMemorySize, ATTN_SMEM);
    cudaFuncSetAttribute(proj_kernel,
                         cudaFuncAttributeMaxDynamicSharedMemorySize, XW_SMEM);

    prepass_elem_kernel<<<6656, 256>>>(keys, W_out, mask);
    vt_kernel<<<dim3(SEQ / 64, HEADS, N_BATCH), 256>>>(values);
    attn_kernel<<<dim3(SEQ / 128, HEADS, N_BATCH), 256, ATTN_SMEM>>>(query);
    proj_kernel<<<dim3((N_BATCH * SEQ) / 128, EMBED / 128), 512, XW_SMEM>>>(b_out, out);
}